// round 2
// baseline (speedup 1.0000x reference)
#include <cuda_runtime.h>
#include <mma.h>
#include <math.h>

using namespace nvcuda;

namespace {
constexpr int NV = 512;   // nodes
constexpr int C  = 256;   // channels
constexpr int MT = 64;    // j-tile rows
constexpr int LDA = 264;  // padded A leading dim (floats); 264*4 bytes % 16 == 0
constexpr int NWARP = 8;  // 256 threads

// smem layout (floats)
constexpr int SM_A   = 0;                 // [MT][LDA]
constexpr int SM_Q   = SM_A + MT * LDA;   // [MT][C]  q-tilde stage
constexpr int SM_VE  = SM_Q + MT * C;     // [MT][C]  Gv stage
constexpr int SM_N   = SM_VE + MT * C;    // [C]      n_i
constexpr int SM_BK  = SM_N + C;          // [C]      bk
constexpr int SM_SC  = SM_BK + C;         // [MT]     scores
constexpr int SM_RED = SM_SC + MT;        // [NWARP]
constexpr int SMEM_FLOATS = SM_RED + NWARP;
constexpr int SMEM_BYTES  = SMEM_FLOATS * 4;   // ~201 KB
}

struct AccFrags {
    wmma::fragment<wmma::accumulator, 16, 16, 8, float> acc[4][2];
};

// GEMM: (64 x 256 A-tile in smem) @ W^T. W row-major (d,c) read as col-major B
// with ld=C. Warp `wid` produces output columns [wid*32, wid*32+32).
__device__ __forceinline__ void gemm_acc(AccFrags& f, const float* sA,
                                         const float* __restrict__ W, int wid) {
    wmma::fragment<wmma::matrix_a, 16, 16, 8, wmma::precision::tf32, wmma::row_major> af[4];
    wmma::fragment<wmma::matrix_b, 16, 16, 8, wmma::precision::tf32, wmma::col_major> bf[2];
#pragma unroll
    for (int m = 0; m < 4; m++)
#pragma unroll
        for (int nn = 0; nn < 2; nn++) wmma::fill_fragment(f.acc[m][nn], 0.0f);

    const float* Wbase = W + (size_t)(wid * 32) * C;
    for (int k = 0; k < C; k += 8) {
#pragma unroll
        for (int m = 0; m < 4; m++) {
            wmma::load_matrix_sync(af[m], sA + m * 16 * LDA + k, LDA);
#pragma unroll
            for (int t = 0; t < af[m].num_elements; t++)
                af[m].x[t] = wmma::__float_to_tf32(af[m].x[t]);
        }
#pragma unroll
        for (int nn = 0; nn < 2; nn++) {
            wmma::load_matrix_sync(bf[nn], Wbase + (size_t)nn * 16 * C + k, C);
#pragma unroll
            for (int t = 0; t < bf[nn].num_elements; t++)
                bf[nn].x[t] = wmma::__float_to_tf32(bf[nn].x[t]);
        }
#pragma unroll
        for (int m = 0; m < 4; m++)
#pragma unroll
            for (int nn = 0; nn < 2; nn++)
                wmma::mma_sync(f.acc[m][nn], af[m], bf[nn], f.acc[m][nn]);
    }
}

__device__ __forceinline__ void frag_store(AccFrags& f, float* dst, int ldm, int wid) {
#pragma unroll
    for (int m = 0; m < 4; m++)
#pragma unroll
        for (int nn = 0; nn < 2; nn++)
            wmma::store_matrix_sync(dst + m * 16 * ldm + wid * 32 + nn * 16,
                                    f.acc[m][nn], ldm, wmma::mem_row_major);
}

// A[j][c] = n_i[c] * n_j[c] * s[i, j0+j, c]  (float4-vectorized)
__device__ __forceinline__ void build_tile(float* sA, const float* sn,
                                           const float* __restrict__ nmat,
                                           const float* __restrict__ s,
                                           int i, int j0, int tid) {
#pragma unroll 4
    for (int idx = tid; idx < MT * (C / 4); idx += 256) {
        const int j  = idx >> 6;
        const int c4 = (idx & 63) * 4;
        const float4 n4  = *reinterpret_cast<const float4*>(nmat + (size_t)(j0 + j) * C + c4);
        const float4 s4  = *reinterpret_cast<const float4*>(s + ((size_t)i * NV + j0 + j) * C + c4);
        const float4 sn4 = *reinterpret_cast<const float4*>(sn + c4);
        float4 r;
        r.x = sn4.x * n4.x * s4.x;
        r.y = sn4.y * n4.y * s4.y;
        r.z = sn4.z * n4.z * s4.z;
        r.w = sn4.w * n4.w * s4.w;
        *reinterpret_cast<float4*>(sA + j * LDA + c4) = r;
    }
}

// Fused: per node i, stream 8 j-tiles with online softmax.
//   q~ = (A Wq^T + bq) * v^2        (both v factors of q.k folded into q~)
//   score_j = sum_d q~_jd (Gk_jd + bk_d) / 16
//   x_i = (sum_j e^{s_j - m} (Gv_j + bv) * v_j) / l ;  out = (x+n)/||x+n||
__global__ __launch_bounds__(256) void fused_kernel(
    const float* __restrict__ nmat, const float* __restrict__ s, const float* __restrict__ v,
    const float* __restrict__ Wq, const float* __restrict__ bq,
    const float* __restrict__ Wk, const float* __restrict__ bk,
    const float* __restrict__ Wv, const float* __restrict__ bv,
    float* __restrict__ out)
{
    extern __shared__ float sm[];
    float* sA  = sm + SM_A;
    float* sQ  = sm + SM_Q;
    float* sVe = sm + SM_VE;
    float* sn  = sm + SM_N;
    float* sbk = sm + SM_BK;
    float* ssc = sm + SM_SC;
    float* red = sm + SM_RED;

    const int i = blockIdx.x;
    const int tid = threadIdx.x;
    const int wid = tid >> 5, lane = tid & 31;

    sn[tid]  = nmat[(size_t)i * C + tid];
    sbk[tid] = bk[tid];
    const float bqd = bq[tid], bvd = bv[tid];

    float m_run = -1e30f, l_run = 0.0f, xacc = 0.0f;

    for (int jt = 0; jt < NV / MT; jt++) {
        const int j0 = jt * MT;
        __syncthreads();                       // prev-iter smem readers done
        build_tile(sA, sn, nmat, s, i, j0, tid);
        __syncthreads();

        AccFrags f;
        gemm_acc(f, sA, Wq, wid); frag_store(f, sQ, C, wid);
        gemm_acc(f, sA, Wv, wid); frag_store(f, sVe, C, wid);
        gemm_acc(f, sA, Wk, wid);              // compute only; sA still live
        __syncthreads();                       // all warps done reading sA
        frag_store(f, sA, LDA, wid);           // Gk overwrites A
        // fold bq and v^2 into q-tilde (thread owns channel tid)
        {
            const float* vrow = v + ((size_t)i * NV + j0) * C + tid;
#pragma unroll 4
            for (int j = 0; j < MT; j++) {
                const float vv = vrow[(size_t)j * C];
                sQ[j * C + tid] = (sQ[j * C + tid] + bqd) * vv * vv;
            }
        }
        __syncthreads();                       // Gk + q~ visible

        // scores: warp handles MT/NWARP rows
#pragma unroll
        for (int r = 0; r < MT / NWARP; r++) {
            const int j = wid * (MT / NWARP) + r;
            float p = 0.0f;
#pragma unroll 4
            for (int d = lane; d < C; d += 32)
                p += sQ[j * C + d] * (sA[j * LDA + d] + sbk[d]);
#pragma unroll
            for (int o = 16; o > 0; o >>= 1) p += __shfl_xor_sync(0xffffffffu, p, o);
            if (lane == 0) ssc[j] = p * 0.0625f;   // 1/sqrt(256)
        }
        __syncthreads();

        // online softmax update (every thread replays identical scalar math)
        float tm = -1e30f;
#pragma unroll 8
        for (int j = 0; j < MT; j++) tm = fmaxf(tm, ssc[j]);
        const float m_new = fmaxf(m_run, tm);
        const float scale = __expf(m_run - m_new);
        xacc *= scale;
        l_run *= scale;
        {
            const float* vrow = v + ((size_t)i * NV + j0) * C + tid;
#pragma unroll 4
            for (int j = 0; j < MT; j++) {
                const float p = __expf(ssc[j] - m_new);
                l_run += p;
                xacc += p * (sVe[j * C + tid] + bvd) * vrow[(size_t)j * C];
            }
        }
        m_run = m_new;
    }

    // residual + L2 normalize
    const float x = xacc / l_run + sn[tid];
    float sq = x * x;
#pragma unroll
    for (int o = 16; o > 0; o >>= 1) sq += __shfl_xor_sync(0xffffffffu, sq, o);
    __syncthreads();
    if (lane == 0) red[wid] = sq;
    __syncthreads();
    float tot = 0.0f;
#pragma unroll
    for (int w = 0; w < NWARP; w++) tot += red[w];
    out[(size_t)i * C + tid] = x * rsqrtf(tot);
}

extern "C" void kernel_launch(void* const* d_in, const int* in_sizes, int n_in,
                              void* d_out, int out_size) {
    const float* nmat = (const float*)d_in[0];
    const float* s    = (const float*)d_in[1];
    const float* v    = (const float*)d_in[2];
    const float* Wq   = (const float*)d_in[3];
    const float* bq   = (const float*)d_in[4];
    const float* Wk   = (const float*)d_in[5];
    const float* bk   = (const float*)d_in[6];
    const float* Wv   = (const float*)d_in[7];
    const float* bv   = (const float*)d_in[8];

    cudaFuncSetAttribute(fused_kernel, cudaFuncAttributeMaxDynamicSharedMemorySize, SMEM_BYTES);
    fused_kernel<<<NV, 256, SMEM_BYTES>>>(nmat, s, v, Wq, bq, Wk, bk, Wv, bv, (float*)d_out);
}